// round 3
// baseline (speedup 1.0000x reference)
#include <cuda_runtime.h>
#include <cstdint>

#define NSTEPS 2176
#define BURN   128
#define DWALK  512
#define HMLP   1024

// ---------------- scratch (no allocations allowed) ----------------
__device__ __align__(16) float g_M [NSTEPS * DWALK];   // 0.1 * noise_t  [2176,512]
__device__ __align__(16) float g_ZD[NSTEPS * HMLP];    // M @ W1         [2176,1024]
__device__ float g_U[NSTEPS];                          // uniform u_t

// ---------------- threefry2x32 (Random123 / JAX exact) ----------------
__device__ __forceinline__ uint32_t rotl32(uint32_t x, int r) {
    return (x << r) | (x >> (32 - r));
}

__device__ __forceinline__ void threefry2x32(uint32_t k0, uint32_t k1,
                                             uint32_t c0, uint32_t c1,
                                             uint32_t& o0, uint32_t& o1) {
    uint32_t ks2 = 0x1BD11BDAu ^ k0 ^ k1;
    uint32_t x0 = c0 + k0;
    uint32_t x1 = c1 + k1;
#define TF_RND(r) { x0 += x1; x1 = rotl32(x1, r); x1 ^= x0; }
    TF_RND(13) TF_RND(15) TF_RND(26) TF_RND(6)
    x0 += k1;  x1 += ks2 + 1u;
    TF_RND(17) TF_RND(29) TF_RND(16) TF_RND(24)
    x0 += ks2; x1 += k0 + 2u;
    TF_RND(13) TF_RND(15) TF_RND(26) TF_RND(6)
    x0 += k0;  x1 += k1 + 3u;
    TF_RND(17) TF_RND(29) TF_RND(16) TF_RND(24)
    x0 += k1;  x1 += ks2 + 4u;
    TF_RND(13) TF_RND(15) TF_RND(26) TF_RND(6)
    x0 += ks2; x1 += k0 + 5u;
#undef TF_RND
    o0 = x0; o1 = x1;
}

// bits -> float in [0,1): ((b>>9)|0x3f800000) as float - 1  (JAX _uniform)
__device__ __forceinline__ float bits_to_f01(uint32_t b) {
    return __fadd_rn(__uint_as_float((b >> 9) | 0x3F800000u), -1.0f);
}

// XLA ErfInv f32 (Giles polynomial; XLA emits mul+add WITHOUT fma contraction)
__device__ __forceinline__ float erfinv_xla(float x) {
    float w = -log1pf(-__fmul_rn(x, x));
    float p;
    if (w < 5.0f) {
        w = __fadd_rn(w, -2.5f);
        p = 2.81022636e-08f;
        p = __fadd_rn(__fmul_rn(p, w), 3.43273939e-07f);
        p = __fadd_rn(__fmul_rn(p, w), -3.5233877e-06f);
        p = __fadd_rn(__fmul_rn(p, w), -4.39150654e-06f);
        p = __fadd_rn(__fmul_rn(p, w), 0.00021858087f);
        p = __fadd_rn(__fmul_rn(p, w), -0.00125372503f);
        p = __fadd_rn(__fmul_rn(p, w), -0.00417768164f);
        p = __fadd_rn(__fmul_rn(p, w), 0.246640727f);
        p = __fadd_rn(__fmul_rn(p, w), 1.50140941f);
    } else {
        w = __fadd_rn(__fsqrt_rn(w), -3.0f);
        p = -0.000200214257f;
        p = __fadd_rn(__fmul_rn(p, w), 0.000100950558f);
        p = __fadd_rn(__fmul_rn(p, w), 0.00134934322f);
        p = __fadd_rn(__fmul_rn(p, w), -0.00367342844f);
        p = __fadd_rn(__fmul_rn(p, w), 0.00573950773f);
        p = __fadd_rn(__fmul_rn(p, w), -0.0076224613f);
        p = __fadd_rn(__fmul_rn(p, w), 0.00943887047f);
        p = __fadd_rn(__fmul_rn(p, w), 1.00167406f);
        p = __fadd_rn(__fmul_rn(p, w), 2.83297682f);
    }
    return __fmul_rn(p, x);
}

// JAX normal: u = uniform(key, lo=nextafter(-1,0), hi=1); sqrt(2)*erfinv(u)
// (hi-lo) rounds to exactly 2.0f; f*2 is exact.
__device__ __forceinline__ float normal_from_bits(uint32_t b) {
    const float lo = -0.99999994f;  // nextafter(-1f, 0f)
    float f = bits_to_f01(b);
    float u = fmaxf(lo, __fadd_rn(__fmul_rn(f, 2.0f), lo));
    return __fmul_rn(1.4142135381698608f, erfinv_xla(u));  // float32(sqrt(2))
}

// XLA Tanh f32 emitter (clamp 7.90531110763549805, rational poly, no fma)
__device__ __forceinline__ float tanh_xla(float x) {
    const float kClamp = 7.90531110763549805f;
    float xc = fminf(fmaxf(x, -kClamp), kClamp);
    float x2 = __fmul_rn(xc, xc);
    float p = -2.76076847742355e-16f;
    p = __fadd_rn(__fmul_rn(p, x2), 2.00018790482477e-13f);
    p = __fadd_rn(__fmul_rn(p, x2), -8.60467152213735e-11f);
    p = __fadd_rn(__fmul_rn(p, x2), 5.12229709037114e-08f);
    p = __fadd_rn(__fmul_rn(p, x2), 1.48572235717979e-05f);
    p = __fadd_rn(__fmul_rn(p, x2), 6.37261928875436e-04f);
    p = __fadd_rn(__fmul_rn(p, x2), 4.89352455891786e-03f);
    float num = __fmul_rn(xc, p);
    float q = 1.19825839466702e-06f;
    q = __fadd_rn(__fmul_rn(q, x2), 1.18534705686654e-04f);
    q = __fadd_rn(__fmul_rn(q, x2), 2.26843463243900e-03f);
    q = __fadd_rn(__fmul_rn(q, x2), 4.89352518554385e-03f);
    float r = __fdiv_rn(num, q);
    return (fabsf(x) < 0.0004f) ? x : r;
}

// ---------------- kernel 1: per-step keys, uniforms, normals ----------------
// jax_threefry_partitionable=True semantics:
//   split(key, n)[t]              = full output pair of TF(key, (0, t))
//   random_bits(key,32,shape)[i]  = o0 ^ o1 of TF(key, (0, i))
// Chain per step t:
//   (kt)      = TF((0,1), 0, t)
//   k_noise   = TF(kt, 0, 0)   k_unif = TF(kt, 0, 1)
//   u_t       = b2f01(o0^o1 of TF(k_unif, 0, 0))            (minval 0 -> identity)
//   n_t[i]    = normal(o0^o1 of TF(k_noise, 0, i)), i<512
__global__ void gen_kernel() {
    int t = blockIdx.x;
    int i = threadIdx.x;  // 0..511

    // key chain (computed redundantly per thread; ~3 threefrys, cheap)
    uint32_t kt0, kt1, kn0, kn1;
    threefry2x32(0u, 1u, 0u, (uint32_t)t, kt0, kt1);
    threefry2x32(kt0, kt1, 0u, 0u, kn0, kn1);

    if (i == 0) {
        uint32_t ku0, ku1, ua, ub;
        threefry2x32(kt0, kt1, 0u, 1u, ku0, ku1);
        threefry2x32(ku0, ku1, 0u, 0u, ua, ub);
        g_U[t] = bits_to_f01(ua ^ ub);
    }

    uint32_t r0, r1;
    threefry2x32(kn0, kn1, 0u, (uint32_t)i, r0, r1);
    g_M[t * DWALK + i] = __fmul_rn(normal_from_bits(r0 ^ r1), 0.1f);
}

// ---------------- kernel 2: fp32 SGEMM  ZD = M @ W1 ----------------
// M [2176,512] row-major, W1 [512,1024] row-major, ZD [2176,1024].
// Tiles: 64x64x16, 256 threads, 4x4 per thread. Dims divide exactly.
__global__ void __launch_bounds__(256) gemm_kernel(const float* __restrict__ W1) {
    const int BK = 16;
    __shared__ float As[BK][64];   // transposed A tile
    __shared__ float Bs[BK][64];

    int tid = threadIdx.x;
    int tx = tid & 15;        // 0..15
    int ty = tid >> 4;        // 0..15
    int rowBase = blockIdx.y * 64;
    int colBase = blockIdx.x * 64;

    int aRow = tid >> 2;            // 0..63
    int aCol = (tid & 3) * 4;       // 0,4,8,12
    int bRow = tid >> 4;            // 0..15
    int bCol = (tid & 15) * 4;      // 0..60

    float acc[4][4] = {{0.f}};

    for (int k0 = 0; k0 < 512; k0 += BK) {
        float4 av = *reinterpret_cast<const float4*>(&g_M[(rowBase + aRow) * 512 + k0 + aCol]);
        float4 bv = *reinterpret_cast<const float4*>(&W1[(k0 + bRow) * 1024 + colBase + bCol]);
        As[aCol + 0][aRow] = av.x;
        As[aCol + 1][aRow] = av.y;
        As[aCol + 2][aRow] = av.z;
        As[aCol + 3][aRow] = av.w;
        *reinterpret_cast<float4*>(&Bs[bRow][bCol]) = bv;
        __syncthreads();
#pragma unroll
        for (int k = 0; k < BK; k++) {
            float4 a = *reinterpret_cast<float4*>(&As[k][ty * 4]);
            float4 b = *reinterpret_cast<float4*>(&Bs[k][tx * 4]);
            float ar[4] = {a.x, a.y, a.z, a.w};
            float br[4] = {b.x, b.y, b.z, b.w};
#pragma unroll
            for (int i = 0; i < 4; i++)
#pragma unroll
                for (int j = 0; j < 4; j++)
                    acc[i][j] = fmaf(ar[i], br[j], acc[i][j]);
        }
        __syncthreads();
    }
#pragma unroll
    for (int i = 0; i < 4; i++) {
#pragma unroll
        for (int j = 0; j < 4; j++) {
            g_ZD[(rowBase + ty * 4 + i) * 1024 + colBase + tx * 4 + j] = acc[i][j];
        }
    }
}

// ---------------- kernel 3: sequential MH chain (1 CTA, 1024 threads) ----------------
__global__ void __launch_bounds__(1024, 1)
chain_kernel(const float* __restrict__ x0, const float* __restrict__ W1,
             const float* __restrict__ b1, const float* __restrict__ W2,
             const float* __restrict__ b2, float* __restrict__ out) {
    __shared__ float s_x0[DWALK];
    __shared__ float s_part[32];
    __shared__ uint32_t s_acc;

    int tid  = threadIdx.x;          // 0..1023 (one per hidden unit)
    int lane = tid & 31;
    int wid  = tid >> 5;

    if (tid < DWALK) s_x0[tid] = x0[tid];
    __syncthreads();

    // z0 = dot(x0, W1[:, tid]) — coalesced across threads
    float z = 0.f;
#pragma unroll 8
    for (int k = 0; k < DWALK; k++)
        z = fmaf(s_x0[k], W1[k * 1024 + tid], z);

    float b1v = b1[tid];
    float w2v = W2[tid];
    float b2v = b2[0];
    float x   = (tid < DWALK) ? s_x0[tid] : 0.f;

    // p_old = psi2(x0)
    float p_old = 0.f;
    {
        float h = tanh_xla(z + b1v);
        float v = __fmul_rn(h, w2v);
#pragma unroll
        for (int o = 16; o > 0; o >>= 1) v += __shfl_down_sync(0xffffffffu, v, o);
        if (lane == 0) s_part[wid] = v;
        __syncthreads();
        if (wid == 0) {
            float r = s_part[lane];
#pragma unroll
            for (int o = 16; o > 0; o >>= 1) r += __shfl_down_sync(0xffffffffu, r, o);
            if (lane == 0) {
                float mdl = __fadd_rn(r, b2v);
                p_old = __fmul_rn(mdl, mdl);
            }
        }
        __syncthreads();  // protect s_part before loop reuse
    }

    // prefetch step 0
    float zd   = g_ZD[tid];
    float mval = (tid < DWALK) ? g_M[tid] : 0.f;
    float uval = (tid == 0) ? g_U[0] : 0.f;

    for (int t = 0; t < NSTEPS; t++) {
        float znew = z + zd;
        float hh   = tanh_xla(znew + b1v);
        float pv   = __fmul_rn(hh, w2v);

        // prefetch next step (t-indexed only — independent of accept outcomes)
        float zd_n = 0.f, m_n = 0.f, u_n = 0.f;
        if (t + 1 < NSTEPS) {
            zd_n = g_ZD[(t + 1) * 1024 + tid];
            if (tid < DWALK) m_n = g_M[(t + 1) * DWALK + tid];
            if (tid == 0)    u_n = g_U[t + 1];
        }

        // block reduce (order fixed & deterministic)
#pragma unroll
        for (int o = 16; o > 0; o >>= 1) pv += __shfl_down_sync(0xffffffffu, pv, o);
        if (lane == 0) s_part[wid] = pv;
        __syncthreads();
        if (wid == 0) {
            float r = s_part[lane];
#pragma unroll
            for (int o = 16; o > 0; o >>= 1) r += __shfl_down_sync(0xffffffffu, r, o);
            if (lane == 0) {
                float mdl   = __fadd_rn(r, b2v);
                float p_new = __fmul_rn(mdl, mdl);
                float ratio = fminf(__fdiv_rn(p_new, __fadd_rn(p_old, 1e-12f)), 1.0f);
                uint32_t acc = (uval < ratio) ? 1u : 0u;
                if (acc) p_old = p_new;
                s_acc = acc;
            }
        }
        __syncthreads();
        uint32_t acc = s_acc;

        if (acc) z = znew;
        if (tid < DWALK) {
            if (acc) x = __fadd_rn(x, mval);
            if (t >= BURN) out[(t - BURN) * DWALK + tid] = x;
        }
        zd = zd_n; mval = m_n; uval = u_n;
    }
}

// ---------------- launch ----------------
extern "C" void kernel_launch(void* const* d_in, const int* in_sizes, int n_in,
                              void* d_out, int out_size) {
    const float* x0 = (const float*)d_in[0];
    const float* W1 = (const float*)d_in[1];
    const float* b1 = (const float*)d_in[2];
    const float* W2 = (const float*)d_in[3];
    const float* b2 = (const float*)d_in[4];
    float* out = (float*)d_out;

    gen_kernel<<<NSTEPS, DWALK>>>();
    gemm_kernel<<<dim3(1024 / 64, NSTEPS / 64), 256>>>(W1);
    chain_kernel<<<1, 1024>>>(x0, W1, b1, W2, b2, out);
}

// round 6
// speedup vs baseline: 1.3313x; 1.3313x over previous
#include <cuda_runtime.h>
#include <cstdint>

#define NSTEPS 2176
#define BURN   128
#define DWALK  512
#define HMLP   1024

// ---------------- scratch (no allocations allowed) ----------------
__device__ __align__(16) float g_M [NSTEPS * DWALK];   // 0.1 * noise_t  [2176,512]
__device__ __align__(16) float g_ZD[NSTEPS * HMLP];    // M @ W1         [2176,1024]
__device__ float g_U[NSTEPS];                          // uniform u_t

// ---------------- threefry2x32 (Random123 / JAX exact) ----------------
__device__ __forceinline__ uint32_t rotl32(uint32_t x, int r) {
    return (x << r) | (x >> (32 - r));
}

__device__ __forceinline__ void threefry2x32(uint32_t k0, uint32_t k1,
                                             uint32_t c0, uint32_t c1,
                                             uint32_t& o0, uint32_t& o1) {
    uint32_t ks2 = 0x1BD11BDAu ^ k0 ^ k1;
    uint32_t x0 = c0 + k0;
    uint32_t x1 = c1 + k1;
#define TF_RND(r) { x0 += x1; x1 = rotl32(x1, r); x1 ^= x0; }
    TF_RND(13) TF_RND(15) TF_RND(26) TF_RND(6)
    x0 += k1;  x1 += ks2 + 1u;
    TF_RND(17) TF_RND(29) TF_RND(16) TF_RND(24)
    x0 += ks2; x1 += k0 + 2u;
    TF_RND(13) TF_RND(15) TF_RND(26) TF_RND(6)
    x0 += k0;  x1 += k1 + 3u;
    TF_RND(17) TF_RND(29) TF_RND(16) TF_RND(24)
    x0 += k1;  x1 += ks2 + 4u;
    TF_RND(13) TF_RND(15) TF_RND(26) TF_RND(6)
    x0 += ks2; x1 += k0 + 5u;
#undef TF_RND
    o0 = x0; o1 = x1;
}

// bits -> float in [0,1): ((b>>9)|0x3f800000) as float - 1  (JAX _uniform)
__device__ __forceinline__ float bits_to_f01(uint32_t b) {
    return __fadd_rn(__uint_as_float((b >> 9) | 0x3F800000u), -1.0f);
}

// XLA ErfInv f32 (Giles polynomial; XLA emits mul+add WITHOUT fma contraction)
__device__ __forceinline__ float erfinv_xla(float x) {
    float w = -log1pf(-__fmul_rn(x, x));
    float p;
    if (w < 5.0f) {
        w = __fadd_rn(w, -2.5f);
        p = 2.81022636e-08f;
        p = __fadd_rn(__fmul_rn(p, w), 3.43273939e-07f);
        p = __fadd_rn(__fmul_rn(p, w), -3.5233877e-06f);
        p = __fadd_rn(__fmul_rn(p, w), -4.39150654e-06f);
        p = __fadd_rn(__fmul_rn(p, w), 0.00021858087f);
        p = __fadd_rn(__fmul_rn(p, w), -0.00125372503f);
        p = __fadd_rn(__fmul_rn(p, w), -0.00417768164f);
        p = __fadd_rn(__fmul_rn(p, w), 0.246640727f);
        p = __fadd_rn(__fmul_rn(p, w), 1.50140941f);
    } else {
        w = __fadd_rn(__fsqrt_rn(w), -3.0f);
        p = -0.000200214257f;
        p = __fadd_rn(__fmul_rn(p, w), 0.000100950558f);
        p = __fadd_rn(__fmul_rn(p, w), 0.00134934322f);
        p = __fadd_rn(__fmul_rn(p, w), -0.00367342844f);
        p = __fadd_rn(__fmul_rn(p, w), 0.00573950773f);
        p = __fadd_rn(__fmul_rn(p, w), -0.0076224613f);
        p = __fadd_rn(__fmul_rn(p, w), 0.00943887047f);
        p = __fadd_rn(__fmul_rn(p, w), 1.00167406f);
        p = __fadd_rn(__fmul_rn(p, w), 2.83297682f);
    }
    return __fmul_rn(p, x);
}

// JAX normal: u = uniform(key, lo=nextafter(-1,0), hi=1); sqrt(2)*erfinv(u)
__device__ __forceinline__ float normal_from_bits(uint32_t b) {
    const float lo = -0.99999994f;  // nextafter(-1f, 0f)
    float f = bits_to_f01(b);
    float u = fmaxf(lo, __fadd_rn(__fmul_rn(f, 2.0f), lo));
    return __fmul_rn(1.4142135381698608f, erfinv_xla(u));  // float32(sqrt(2))
}

// XLA Tanh f32 emitter (clamp 7.90531110763549805, rational poly, no fma)
__device__ __forceinline__ float tanh_xla(float x) {
    const float kClamp = 7.90531110763549805f;
    float xc = fminf(fmaxf(x, -kClamp), kClamp);
    float x2 = __fmul_rn(xc, xc);
    float p = -2.76076847742355e-16f;
    p = __fadd_rn(__fmul_rn(p, x2), 2.00018790482477e-13f);
    p = __fadd_rn(__fmul_rn(p, x2), -8.60467152213735e-11f);
    p = __fadd_rn(__fmul_rn(p, x2), 5.12229709037114e-08f);
    p = __fadd_rn(__fmul_rn(p, x2), 1.48572235717979e-05f);
    p = __fadd_rn(__fmul_rn(p, x2), 6.37261928875436e-04f);
    p = __fadd_rn(__fmul_rn(p, x2), 4.89352455891786e-03f);
    float num = __fmul_rn(xc, p);
    float q = 1.19825839466702e-06f;
    q = __fadd_rn(__fmul_rn(q, x2), 1.18534705686654e-04f);
    q = __fadd_rn(__fmul_rn(q, x2), 2.26843463243900e-03f);
    q = __fadd_rn(__fmul_rn(q, x2), 4.89352518554385e-03f);
    float r = __fdiv_rn(num, q);
    return (fabsf(x) < 0.0004f) ? x : r;
}

// ---------------- kernel 1: per-step keys, uniforms, normals ----------------
// jax_threefry_partitionable=True semantics (verified passing R3):
//   split(key, n)[t]             = output pair of TF(key, (0, t))
//   random_bits(key,32,shape)[i] = o0 ^ o1 of TF(key, (0, i))
__global__ void gen_kernel() {
    int t = blockIdx.x;
    int i = threadIdx.x;  // 0..511

    uint32_t kt0, kt1, kn0, kn1;
    threefry2x32(0u, 1u, 0u, (uint32_t)t, kt0, kt1);
    threefry2x32(kt0, kt1, 0u, 0u, kn0, kn1);

    if (i == 0) {
        uint32_t ku0, ku1, ua, ub;
        threefry2x32(kt0, kt1, 0u, 1u, ku0, ku1);
        threefry2x32(ku0, ku1, 0u, 0u, ua, ub);
        g_U[t] = bits_to_f01(ua ^ ub);
    }

    uint32_t r0, r1;
    threefry2x32(kn0, kn1, 0u, (uint32_t)i, r0, r1);
    g_M[t * DWALK + i] = __fmul_rn(normal_from_bits(r0 ^ r1), 0.1f);
}

// ---------------- kernel 2: fp32 SGEMM  ZD = M @ W1 ----------------
// M [2176,512] row-major, W1 [512,1024] row-major, ZD [2176,1024].
// 128x128x8 tile, 256 threads, 8x8 per-thread microtile. 136 blocks ~ 1 wave.
__global__ void __launch_bounds__(256) gemm_kernel(const float* __restrict__ W1) {
    __shared__ float As[8][128];
    __shared__ float Bs[8][128];

    int tid = threadIdx.x;
    int tx = tid & 15;        // 0..15 -> col group
    int ty = tid >> 4;        // 0..15 -> row group
    int rowBase = blockIdx.y * 128;
    int colBase = blockIdx.x * 128;

    int aRow = tid >> 1;            // 0..127
    int aK   = (tid & 1) * 4;       // 0 or 4
    int bK   = tid >> 5;            // 0..7
    int bCol = (tid & 31) * 4;      // 0..124

    float acc[8][8] = {{0.f}};

    for (int k0 = 0; k0 < 512; k0 += 8) {
        float4 av = *reinterpret_cast<const float4*>(&g_M[(rowBase + aRow) * 512 + k0 + aK]);
        float4 bv = *reinterpret_cast<const float4*>(&W1[(k0 + bK) * 1024 + colBase + bCol]);
        As[aK + 0][aRow] = av.x;
        As[aK + 1][aRow] = av.y;
        As[aK + 2][aRow] = av.z;
        As[aK + 3][aRow] = av.w;
        *reinterpret_cast<float4*>(&Bs[bK][bCol]) = bv;
        __syncthreads();
#pragma unroll
        for (int k = 0; k < 8; k++) {
            float4 a0 = *reinterpret_cast<float4*>(&As[k][ty * 8]);
            float4 a1 = *reinterpret_cast<float4*>(&As[k][ty * 8 + 4]);
            float4 b0 = *reinterpret_cast<float4*>(&Bs[k][tx * 8]);
            float4 b1 = *reinterpret_cast<float4*>(&Bs[k][tx * 8 + 4]);
            float ar[8] = {a0.x, a0.y, a0.z, a0.w, a1.x, a1.y, a1.z, a1.w};
            float br[8] = {b0.x, b0.y, b0.z, b0.w, b1.x, b1.y, b1.z, b1.w};
#pragma unroll
            for (int i = 0; i < 8; i++)
#pragma unroll
                for (int j = 0; j < 8; j++)
                    acc[i][j] = fmaf(ar[i], br[j], acc[i][j]);
        }
        __syncthreads();
    }
#pragma unroll
    for (int i = 0; i < 8; i++) {
        int r = rowBase + ty * 8 + i;
        *reinterpret_cast<float4*>(&g_ZD[r * 1024 + colBase + tx * 8]) =
            make_float4(acc[i][0], acc[i][1], acc[i][2], acc[i][3]);
        *reinterpret_cast<float4*>(&g_ZD[r * 1024 + colBase + tx * 8 + 4]) =
            make_float4(acc[i][4], acc[i][5], acc[i][6], acc[i][7]);
    }
}

// ---------------- kernel 3: sequential MH chain (1 CTA, 512 threads) ----------------
// Thread tid owns hidden units (2*tid, 2*tid+1) and walker dim tid.
// One __syncthreads per step: warp partials -> parity-double-buffered smem ->
// every thread redundantly computes the same fixed-order sum + accept decision.
__global__ void __launch_bounds__(512, 1)
chain_kernel(const float* __restrict__ x0, const float* __restrict__ W1,
             const float* __restrict__ b1, const float* __restrict__ W2,
             const float* __restrict__ b2, float* __restrict__ out) {
    __shared__ float s_x0[DWALK];
    __shared__ __align__(16) float s_part[2][16];

    int tid  = threadIdx.x;          // 0..511
    int lane = tid & 31;
    int wid  = tid >> 5;             // 0..15

    s_x0[tid] = x0[tid];
    __syncthreads();

    // z0,z1 = dot(x0, W1[:, 2*tid]), dot(x0, W1[:, 2*tid+1])
    float z0 = 0.f, z1 = 0.f;
#pragma unroll 8
    for (int k = 0; k < DWALK; k++) {
        float xv = s_x0[k];
        float2 w = *reinterpret_cast<const float2*>(&W1[k * 1024 + 2 * tid]);
        z0 = fmaf(xv, w.x, z0);
        z1 = fmaf(xv, w.y, z1);
    }

    float2 b1v = *reinterpret_cast<const float2*>(&b1[2 * tid]);
    float2 w2v = *reinterpret_cast<const float2*>(&W2[2 * tid]);
    float  b2v = b2[0];
    float  x   = s_x0[tid];

    // fixed-order sum of the 16 warp partials (identical on every thread)
    auto tree16 = [&](const float* sp) -> float {
        float4 q0 = *reinterpret_cast<const float4*>(sp);
        float4 q1 = *reinterpret_cast<const float4*>(sp + 4);
        float4 q2 = *reinterpret_cast<const float4*>(sp + 8);
        float4 q3 = *reinterpret_cast<const float4*>(sp + 12);
        float s0 = __fadd_rn(__fadd_rn(q0.x, q0.y), __fadd_rn(q0.z, q0.w));
        float s1 = __fadd_rn(__fadd_rn(q1.x, q1.y), __fadd_rn(q1.z, q1.w));
        float s2 = __fadd_rn(__fadd_rn(q2.x, q2.y), __fadd_rn(q2.z, q2.w));
        float s3 = __fadd_rn(__fadd_rn(q3.x, q3.y), __fadd_rn(q3.z, q3.w));
        return __fadd_rn(__fadd_rn(s0, s1), __fadd_rn(s2, s3));
    };

    // ---- p_old = psi2(x0) (uses buffer 1; loop t=0 uses buffer 0) ----
    float p_old;
    {
        float h0 = tanh_xla(__fadd_rn(z0, b1v.x));
        float h1 = tanh_xla(__fadd_rn(z1, b1v.y));
        float pv = __fadd_rn(__fmul_rn(h0, w2v.x), __fmul_rn(h1, w2v.y));
#pragma unroll
        for (int o = 16; o > 0; o >>= 1) pv += __shfl_down_sync(0xffffffffu, pv, o);
        if (lane == 0) s_part[1][wid] = pv;
        __syncthreads();
        float mdl = __fadd_rn(tree16(s_part[1]), b2v);
        p_old = __fmul_rn(mdl, mdl);
    }

    // prefetch step 0 (all indices depend only on t, never on accepts)
    float2 zd   = *reinterpret_cast<const float2*>(&g_ZD[2 * tid]);
    float  mval = g_M[tid];
    float  uval = g_U[0];

    for (int t = 0; t < NSTEPS; t++) {
        float znew0 = __fadd_rn(z0, zd.x);
        float znew1 = __fadd_rn(z1, zd.y);
        float h0 = tanh_xla(__fadd_rn(znew0, b1v.x));
        float h1 = tanh_xla(__fadd_rn(znew1, b1v.y));
        float pv = __fadd_rn(__fmul_rn(h0, w2v.x), __fmul_rn(h1, w2v.y));

        // prefetch next step (overlaps with the reduction below)
        float2 zd_n = make_float2(0.f, 0.f);
        float  m_n = 0.f, u_n = 0.f;
        if (t + 1 < NSTEPS) {
            zd_n = *reinterpret_cast<const float2*>(&g_ZD[(t + 1) * 1024 + 2 * tid]);
            m_n  = g_M[(t + 1) * DWALK + tid];
            u_n  = g_U[t + 1];
        }

#pragma unroll
        for (int o = 16; o > 0; o >>= 1) pv += __shfl_down_sync(0xffffffffu, pv, o);
        if (lane == 0) s_part[t & 1][wid] = pv;
        __syncthreads();

        // every thread: identical decision from identical smem data
        float mdl   = __fadd_rn(tree16(s_part[t & 1]), b2v);
        float p_new = __fmul_rn(mdl, mdl);
        float ratio = fminf(__fdiv_rn(p_new, __fadd_rn(p_old, 1e-12f)), 1.0f);
        bool  acc   = (uval < ratio);

        if (acc) {
            p_old = p_new;
            z0 = znew0; z1 = znew1;
            x  = __fadd_rn(x, mval);
        }
        if (t >= BURN) out[(t - BURN) * DWALK + tid] = x;

        zd = zd_n; mval = m_n; uval = u_n;
    }
}

// ---------------- launch ----------------
extern "C" void kernel_launch(void* const* d_in, const int* in_sizes, int n_in,
                              void* d_out, int out_size) {
    const float* x0 = (const float*)d_in[0];
    const float* W1 = (const float*)d_in[1];
    const float* b1 = (const float*)d_in[2];
    const float* W2 = (const float*)d_in[3];
    const float* b2 = (const float*)d_in[4];
    float* out = (float*)d_out;

    gen_kernel<<<NSTEPS, DWALK>>>();
    gemm_kernel<<<dim3(HMLP / 128, NSTEPS / 128), 256>>>(W1);
    chain_kernel<<<1, 512>>>(x0, W1, b1, W2, b2, out);
}